// round 17
// baseline (speedup 1.0000x reference)
#include <cuda_runtime.h>
#include <cuda_bf16.h>
#include <math.h>
#include <stdint.h>

#define KN 4096
#define CN 10
#define DN 128
#define BN 1000
#define LN 512
#define NTILES 4096            // (4096/32 j) x (4096/128 i)
#define UGRID 444              // 148 SMs x 3 CTAs (persistent)

// global accumulators / scratch (no device allocs allowed)
__device__ double g_sup;
__device__ double g_unsup;
__device__ unsigned int g_ctr;
__device__ unsigned int g_tile;
__device__ float  g_sqn[KN];
__device__ float  g_P[KN * 16];                // embs @ W.T, padded to 16/row
__device__ __nv_bfloat16 g_embs_bf[KN * DN];   // 1MB bf16 copy of embs

static __device__ __forceinline__ uint32_t smem_u32(const void* p) {
    uint32_t a;
    asm("{ .reg .u64 t; cvta.to.shared.u64 t, %1; cvt.u32.u64 %0, t; }"
        : "=r"(a) : "l"(p));
    return a;
}
static __device__ __forceinline__ void ldsm_x4(uint32_t* r, uint32_t addr) {
    asm volatile("ldmatrix.sync.aligned.m8n8.x4.shared.b16 {%0,%1,%2,%3}, [%4];"
                 : "=r"(r[0]), "=r"(r[1]), "=r"(r[2]), "=r"(r[3]) : "r"(addr));
}
static __device__ __forceinline__ void ldsm_x2(uint32_t* r, uint32_t addr) {
    asm volatile("ldmatrix.sync.aligned.m8n8.x2.shared.b16 {%0,%1}, [%2];"
                 : "=r"(r[0]), "=r"(r[1]) : "r"(addr));
}
static __device__ __forceinline__ void mma_bf16(float* c, const uint32_t* a,
                                                const uint32_t* b) {
    asm volatile(
        "mma.sync.aligned.m16n8k16.row.col.f32.bf16.bf16.f32 "
        "{%0,%1,%2,%3}, {%4,%5,%6,%7}, {%8,%9}, {%0,%1,%2,%3};"
        : "+f"(c[0]), "+f"(c[1]), "+f"(c[2]), "+f"(c[3])
        : "r"(a[0]), "r"(a[1]), "r"(a[2]), "r"(a[3]), "r"(b[0]), "r"(b[1]));
}
static __device__ __forceinline__ float sqrt_approx(float x) {
    float r;
    asm("sqrt.approx.f32 %0, %1;" : "=f"(r) : "f"(x));
    return r;
}
static __device__ __forceinline__ void cp_async16(uint32_t saddr, const void* g) {
    asm volatile("cp.async.cg.shared.global [%0], [%1], 16;"
                 :: "r"(saddr), "l"(g) : "memory");
}

// ---------------------------------------------------------------------------
// prep: init + bf16 convert + sqn + P = embs @ W.T
// ---------------------------------------------------------------------------
__global__ __launch_bounds__(256)
void prep_kernel(const float* __restrict__ embs,
                 const float* __restrict__ W) {
    __shared__ float s_w[CN * DN];

    int tid = threadIdx.x;
    if (blockIdx.x == 0 && tid == 0) {
        g_sup = 0.0;
        g_unsup = 0.0;
        g_ctr = 0u;
        g_tile = 0u;
    }
    for (int i = tid; i < CN * DN; i += 256) s_w[i] = W[i];
    __syncthreads();

    int wid = tid >> 5, lane = tid & 31;
    int row0 = (blockIdx.x * 8 + wid) * 4;    // 128*8*4 = 4096 rows

    float4 e[4];
    #pragma unroll
    for (int rr = 0; rr < 4; rr++)
        e[rr] = *(const float4*)(embs + (size_t)(row0 + rr) * DN + lane * 4);

    #pragma unroll
    for (int rr = 0; rr < 4; rr++) {
        __nv_bfloat162* bd =
            (__nv_bfloat162*)(g_embs_bf + (size_t)(row0 + rr) * DN + lane * 4);
        bd[0] = __floats2bfloat162_rn(e[rr].x, e[rr].y);
        bd[1] = __floats2bfloat162_rn(e[rr].z, e[rr].w);
    }

    #pragma unroll
    for (int rr = 0; rr < 4; rr++) {
        float part[CN + 1];
        part[CN] = e[rr].x * e[rr].x + e[rr].y * e[rr].y
                 + e[rr].z * e[rr].z + e[rr].w * e[rr].w;
        #pragma unroll
        for (int c = 0; c < CN; c++) {
            const float4 w4 = *(const float4*)(s_w + c * DN + lane * 4);
            part[c] = e[rr].x * w4.x + e[rr].y * w4.y
                    + e[rr].z * w4.z + e[rr].w * w4.w;
        }
        #pragma unroll
        for (int off = 16; off; off >>= 1)
            #pragma unroll
            for (int c = 0; c <= CN; c++)
                part[c] += __shfl_down_sync(0xffffffffu, part[c], off);
        if (lane == 0) {
            g_sqn[row0 + rr] = part[CN];
            #pragma unroll
            for (int c = 0; c < CN; c++) g_P[(row0 + rr) * 16 + c] = part[c];
        }
    }
}

// ---------------------------------------------------------------------------
// supervised term via P: logits[b] = sum_l P[reads[b,l]]
// ---------------------------------------------------------------------------
__global__ __launch_bounds__(256)
void sup2_kernel(const int* __restrict__ reads,
                 const int* __restrict__ labels) {
    __shared__ float s_part[8][CN];
    __shared__ float s_logit[CN];

    int b = blockIdx.x;
    int tid = threadIdx.x;
    int wid = tid >> 5, lane = tid & 31;

    const int* rrow = reads + (size_t)b * LN;
    float acc[CN] = {};
    #pragma unroll
    for (int q = 0; q < LN / 256; q++) {
        int k = rrow[tid + 256 * q];
        const float* pr = g_P + (size_t)k * 16;
        float4 p0 = *(const float4*)(pr);
        float4 p1 = *(const float4*)(pr + 4);
        float2 p2 = *(const float2*)(pr + 8);
        acc[0] += p0.x; acc[1] += p0.y; acc[2] += p0.z; acc[3] += p0.w;
        acc[4] += p1.x; acc[5] += p1.y; acc[6] += p1.z; acc[7] += p1.w;
        acc[8] += p2.x; acc[9] += p2.y;
    }
    #pragma unroll
    for (int off = 16; off; off >>= 1)
        #pragma unroll
        for (int c = 0; c < CN; c++)
            acc[c] += __shfl_down_sync(0xffffffffu, acc[c], off);
    if (lane == 0) {
        #pragma unroll
        for (int c = 0; c < CN; c++) s_part[wid][c] = acc[c];
    }
    __syncthreads();
    if (tid < CN) {
        float v = 0.f;
        #pragma unroll
        for (int w = 0; w < 8; w++) v += s_part[w][tid];
        s_logit[tid] = v;
    }
    __syncthreads();

    if (tid == 0) {
        float m = s_logit[0];
        #pragma unroll
        for (int c = 1; c < CN; c++) m = fmaxf(m, s_logit[c]);
        float se = 0.f;
        #pragma unroll
        for (int c = 0; c < CN; c++) se += expf(s_logit[c] - m);
        float lse = m + logf(se);
        float contrib = lse - s_logit[labels[b]];   // -logp[label]
        atomicAdd(&g_sup, (double)contrib);
    }
}

// ---------------------------------------------------------------------------
// unsupervised term: persistent CTAs over 128(i) x 32(j) Gram tiles.
// Per tile: cp.async prefetch of the 128x32 pair_counts block overlaps the
// A/B smem fill and the HMMA mainloop; epilogue reads counts from smem.
// 8 warps (2m x 4n); warp tile 64x8; branchless sqrt-only epilogue.
// ---------------------------------------------------------------------------
#define SROW 272                      // bytes per smem row (136 bf16)
#define TILE_A (128 * SROW)           // 34816 B
#define TILE_B (32 * SROW)            // 8704 B
#define SPCROW 160                    // pc smem row stride bytes (40 floats)
#define TILE_PC (128 * SPCROW)        // 20480 B
#define USMEM_TOTAL (TILE_A + TILE_B + TILE_PC + 1024)

__global__ __launch_bounds__(256, 3)
void unsup_mma_kernel(const float* __restrict__ pc,
                      const float* __restrict__ delta_p,
                      float* __restrict__ out) {
    extern __shared__ char dsm[];
    char* s_a  = dsm;
    char* s_b  = dsm + TILE_A;
    char* s_pc = dsm + TILE_A + TILE_B;
    float* s_sqi = (float*)(dsm + TILE_A + TILE_B + TILE_PC);
    float* s_sqj = s_sqi + 128;
    float* s_red = s_sqj + 32;
    __shared__ unsigned int s_tile;

    int tid  = threadIdx.x;
    int wid  = tid >> 5, lane = tid & 31;
    int wm   = wid & 1;          // warp m (2) : 64 rows each
    int wn   = wid >> 1;         // warp n (4) : 8 cols each
    int tq = lane >> 2;          // 0..7
    int tr = lane & 3;           // 0..3

    uint32_t spc_base = smem_u32(s_pc);
    float total = 0.f;

    for (;;) {
        if (tid == 0) s_tile = atomicAdd(&g_tile, 1u);
        __syncthreads();                  // publish s_tile; fence prev epilogue
        unsigned int t = s_tile;
        if (t >= NTILES) break;
        int j0 = (int)(t & 127u) * 32;
        int i0 = (int)(t >> 7) * 128;

        // 1) async prefetch pc tile (128 rows x 32 floats) -> smem
        //    1024 chunks of 16B; thread handles 4 (coalesced by tid)
        #pragma unroll
        for (int k = 0; k < 4; k++) {
            int c  = tid + 256 * k;       // 0..1023
            int r  = c >> 3;              // row 0..127
            int ch = c & 7;               // 16B chunk in row
            cp_async16(spc_base + r * SPCROW + ch * 16,
                       pc + (size_t)(i0 + r) * KN + j0 + ch * 4);
        }
        asm volatile("cp.async.commit_group;" ::: "memory");

        // 2) fill A (128 rows) and B (32 rows) from L2-resident bf16 embs
        const uint4* ga = (const uint4*)(g_embs_bf + (size_t)i0 * DN);
        const uint4* gb = (const uint4*)(g_embs_bf + (size_t)j0 * DN);
        #pragma unroll
        for (int q = 0; q < 8; q++) {
            int idx = tid + 256 * q;
            int r   = idx >> 4;
            int ch  = idx & 15;
            *(uint4*)(s_a + r * SROW + ch * 16) = ga[r * 16 + ch];
        }
        #pragma unroll
        for (int q = 0; q < 2; q++) {
            int idx = tid + 256 * q;      // 0..511
            int r   = idx >> 4;
            int ch  = idx & 15;
            *(uint4*)(s_b + r * SROW + ch * 16) = gb[r * 16 + ch];
        }
        if (tid < 128) s_sqi[tid] = g_sqn[i0 + tid];
        else if (tid < 160) s_sqj[tid - 128] = g_sqn[j0 + tid - 128];
        __syncthreads();

        // 3) HMMA mainloop (pc tile in flight underneath)
        uint32_t aAddr = smem_u32(s_a) + (uint32_t)(wm * 64 + (lane & 15)) * SROW
                       + ((lane >> 4) & 1) * 16;
        uint32_t bAddr = smem_u32(s_b) + (uint32_t)(wn * 8 + (lane & 7)) * SROW
                       + ((lane >> 3) & 1) * 16;

        float acc[4][4] = {};

        #pragma unroll
        for (int kt = 0; kt < 8; kt++) {
            uint32_t af[4][4], bf[2];
            #pragma unroll
            for (int mt = 0; mt < 4; mt++)
                ldsm_x4(af[mt], aAddr + mt * (16 * SROW) + kt * 32);
            ldsm_x2(bf, bAddr + kt * 32);
            #pragma unroll
            for (int mt = 0; mt < 4; mt++)
                mma_bf16(acc[mt], af[mt], bf);
        }

        // 4) wait for pc tile, then branchless epilogue from smem
        asm volatile("cp.async.wait_group 0;" ::: "memory");
        __syncthreads();

        int nn = wn * 8 + tr * 2;
        float sj0 = s_sqj[nn], sj1 = s_sqj[nn + 1];
        #pragma unroll
        for (int mt = 0; mt < 4; mt++) {
            int mlo = wm * 64 + mt * 16 + tq;
            int mhi = mlo + 8;
            float sqlo = s_sqi[mlo];
            float sqhi = s_sqi[mhi];
            float2 c0 = *(const float2*)(s_pc + mlo * SPCROW + nn * 4);
            float2 c1 = *(const float2*)(s_pc + mhi * SPCROW + nn * 4);
            float d2, dist;
            d2 = fmaxf(fmaf(-2.f, acc[mt][0], sqlo + sj0), 0.f);
            dist = sqrt_approx(d2);
            total = fmaf(c0.x, dist, total);
            d2 = fmaxf(fmaf(-2.f, acc[mt][1], sqlo + sj1), 0.f);
            dist = sqrt_approx(d2);
            total = fmaf(c0.y, dist, total);
            d2 = fmaxf(fmaf(-2.f, acc[mt][2], sqhi + sj0), 0.f);
            dist = sqrt_approx(d2);
            total = fmaf(c1.x, dist, total);
            d2 = fmaxf(fmaf(-2.f, acc[mt][3], sqhi + sj1), 0.f);
            dist = sqrt_approx(d2);
            total = fmaf(c1.y, dist, total);
        }
    }

    // one reduce + atomic per CTA
    #pragma unroll
    for (int off = 16; off; off >>= 1)
        total += __shfl_down_sync(0xffffffffu, total, off);
    if (lane == 0) s_red[wid] = total;
    __syncthreads();

    if (tid == 0) {
        float v = 0.f;
        #pragma unroll
        for (int w = 0; w < 8; w++) v += s_red[w];
        atomicAdd(&g_unsup, (double)v);
        __threadfence();
        unsigned int r = atomicAdd(&g_ctr, 1u);
        if (r == UGRID - 1) {
            double sup   = *((volatile double*)&g_sup);
            double unsup = *((volatile double*)&g_unsup);
            float delta = *delta_p;
            double scale = 1.0 / ((double)KN * (double)KN);
            out[0] = delta * (float)sup + (1.f - delta) * (float)(unsup * scale);
        }
    }
}

extern "C" void kernel_launch(void* const* d_in, const int* in_sizes, int n_in,
                              void* d_out, int out_size) {
    const float* pair_counts = (const float*)d_in[0];
    const int*   reads       = (const int*)d_in[1];
    const int*   read_labels = (const int*)d_in[2];
    const float* delta       = (const float*)d_in[3];
    const float* embs        = (const float*)d_in[4];
    const float* softmax_w   = (const float*)d_in[5];
    float* out = (float*)d_out;

    cudaFuncSetAttribute(unsup_mma_kernel,
                         cudaFuncAttributeMaxDynamicSharedMemorySize, USMEM_TOTAL);

    prep_kernel<<<128, 256>>>(embs, softmax_w);
    sup2_kernel<<<BN, 256>>>(reads, read_labels);
    unsup_mma_kernel<<<UGRID, 256, USMEM_TOTAL>>>(pair_counts, delta, out);
}